// round 13
// baseline (speedup 1.0000x reference)
#include <cuda_runtime.h>
#include <math.h>

#define LSEQ 262144
#define NMODE 64
#define TCH 64
#define NCHUNK (LSEQ / TCH)   // 4096
#define WPB 8
#define BTH 256
#define NBLK (NCHUNK / WPB)   // 512 blocks

typedef unsigned long long u64;

// intermediates [mode][chunk]
__device__ __align__(16) float2 g_P[NMODE * NCHUNK];
__device__ __align__(16) float2 g_C[NMODE * NCHUNK];
// grid barrier counters (monotonic across graph replays)
__device__ u64 g_bar1 = 0, g_bar2 = 0;

// ---- packed f32x2 helpers ----
__device__ __forceinline__ u64 pk2(float lo, float hi) {
    u64 r; asm("mov.b64 %0, {%1,%2};" : "=l"(r) : "f"(lo), "f"(hi)); return r;
}
__device__ __forceinline__ void upk2(u64 v, float& lo, float& hi) {
    asm("mov.b64 {%0,%1}, %2;" : "=f"(lo), "=f"(hi) : "l"(v));
}
__device__ __forceinline__ u64 fma2(u64 a, u64 b, u64 c) {
    u64 d; asm("fma.rn.f32x2 %0, %1, %2, %3;" : "=l"(d) : "l"(a), "l"(b), "l"(c)); return d;
}
__device__ __forceinline__ u64 mul2(u64 a, u64 b) {
    u64 d; asm("mul.rn.f32x2 %0, %1, %2;" : "=l"(d) : "l"(a), "l"(b)); return d;
}

// Replay-safe grid barrier: each launch adds exactly NBLK arrivals.
__device__ __forceinline__ void grid_barrier(u64* ctr) {
    __syncthreads();
    if (threadIdx.x == 0) {
        __threadfence();
        u64 old = atomicAdd(ctr, 1ULL);
        u64 target = (old / NBLK + 1) * (u64)NBLK;
        while (*(volatile u64*)ctr < target) __nanosleep(32);
        __threadfence();
    }
    __syncthreads();
}

__global__ __launch_bounds__(BTH) void fused_kernel(
    const float* __restrict__ u, const float* __restrict__ A_re,
    const float* __restrict__ A_im, const float* __restrict__ Cin,
    const float* __restrict__ D, const float* __restrict__ log_step,
    float* __restrict__ y)
{
    __shared__ __align__(16) float su[WPB * TCH];       // 2KB, lives A->C
    __shared__ __align__(16) float2 sP[NMODE][WPB];     // 4KB (partials, then carries)
    __shared__ __align__(16) float red[WPB][32 * 34];   // ~34.8KB transpose-reduce
    __shared__ float sre[BTH], sim_[BTH];               // 2KB scan

    int tid = threadIdx.x, warp = tid >> 5, lane = tid & 31;
    int blk = blockIdx.x;
    int base = blk * (WPB * TCH);

    // ---- per-lane constants for modes (lane, lane+32) ----
    float dt = expf(__ldg(log_step));
    float zr0, zi0, zr1, zi1, cfr0, cfi0, cfr1, cfi1;
    {
        int m = lane;
        float ar = __ldg(&A_re[m]), ai = __ldg(&A_im[m]);
        float e = expf(dt * ar);
        zr0 = e * cosf(dt * ai); zi0 = e * sinf(dt * ai);
        float nr = zr0 - 1.f, ni = zi0;
        float inv = 1.f / (ar * ar + ai * ai);
        float tre = (nr * ar + ni * ai) * inv, tim = (ni * ar - nr * ai) * inv;
        float cr = __ldg(&Cin[2 * m]), ci = __ldg(&Cin[2 * m + 1]);
        cfr0 = cr * tre - ci * tim; cfi0 = cr * tim + ci * tre;
    }
    {
        int m = lane + 32;
        float ar = __ldg(&A_re[m]), ai = __ldg(&A_im[m]);
        float e = expf(dt * ar);
        zr1 = e * cosf(dt * ai); zi1 = e * sinf(dt * ai);
        float nr = zr1 - 1.f, ni = zi1;
        float inv = 1.f / (ar * ar + ai * ai);
        float tre = (nr * ar + ni * ai) * inv, tim = (ni * ar - nr * ai) * inv;
        float cr = __ldg(&Cin[2 * m]), ci = __ldg(&Cin[2 * m + 1]);
        cfr1 = cr * tre - ci * tim; cfi1 = cr * tim + ci * tre;
    }
    u64 Zr = pk2(zr0, zr1), Zi = pk2(zi0, zi1), nZi = pk2(-zi0, -zi1);
    float z2r0 = zr0 * zr0 - zi0 * zi0, z2i0 = 2.f * zr0 * zi0;
    float z2r1 = zr1 * zr1 - zi1 * zi1, z2i1 = 2.f * zr1 * zi1;
    u64 Z2r = pk2(z2r0, z2r1), Z2i = pk2(z2i0, z2i1), nZ2i = pk2(-z2i0, -z2i1);
    float z4r0 = z2r0 * z2r0 - z2i0 * z2i0, z4i0 = 2.f * z2r0 * z2i0;
    float z4r1 = z2r1 * z2r1 - z2i1 * z2i1, z4i1 = 2.f * z2r1 * z2i1;
    u64 Z4r = pk2(z4r0, z4r1), Z4i = pk2(z4i0, z4i1), nZ4i = pk2(-z4i0, -z4i1);
    u64 F = pk2(cfr0, cfr1), nFi = pk2(-cfi0, -cfi1);

    // ================= Phase A: chunk partials (zero-init recurrence) ========
    ((float2*)su)[tid] = ((const float2*)(u + base))[tid];
    __syncthreads();
    {
        u64 sr = 0, si = 0;
        const float4* uw = (const float4*)&su[warp * TCH];
#pragma unroll
        for (int i = 0; i < TCH / 4; i++) {
            float4 uu = uw[i];
            u64 u1p = pk2(uu.x, uu.x), u2p = pk2(uu.y, uu.y);
            u64 u3p = pk2(uu.z, uu.z), u4p = pk2(uu.w, uu.w);
            u64 t1r = fma2(Zr, u1p, u2p), t1i = mul2(Zi, u1p);
            u64 t2r = fma2(Zr, u3p, u4p), t2i = mul2(Zi, u3p);
            u64 br = fma2(Z2r, t1r, fma2(nZ2i, t1i, t2r));
            u64 bi = fma2(Z2i, t1r, fma2(Z2r, t1i, t2i));
            u64 nr = fma2(Z4r, sr, fma2(nZ4i, si, br));
            u64 ni = fma2(Z4i, sr, fma2(Z4r, si, bi));
            sr = nr; si = ni;
        }
        float a, b, c, d;
        upk2(sr, a, b); upk2(si, c, d);
        sP[lane][warp]      = make_float2(a, c);
        sP[lane + 32][warp] = make_float2(b, d);
    }
    __syncthreads();
    {
        int row = tid >> 2, col = (tid & 3) * 2, c0 = blk * WPB;
        *(float4*)&g_P[row * NCHUNK + c0 + col] = *(const float4*)&sP[row][col];
    }
    grid_barrier(&g_bar1);

    // ================= Phase B: per-mode scan (blocks 0..63) =================
    if (blk < NMODE) {
        int mode = blk;
        float ar = __ldg(&A_re[mode]), ai = __ldg(&A_im[mode]);
        float e = expf(dt * ar);
        float wr = e * cosf(dt * ai), wi = e * sinf(dt * ai);
#pragma unroll
        for (int k = 0; k < 6; k++) { float t1 = wr * wr - wi * wi; wi = 2.f * wr * wi; wr = t1; }  // w = z^64
        float Wr = wr, Wi = wi;
#pragma unroll
        for (int k = 0; k < 4; k++) { float t1 = Wr * Wr - Wi * Wi; Wi = 2.f * Wr * Wi; Wr = t1; }  // w^16
        int t = tid;
        float2 p[16];
        const float2* P = &g_P[mode * NCHUNK + 16 * t];
#pragma unroll
        for (int q = 0; q < 8; q++) {
            float4 a = *(const float4*)&P[2 * q];
            p[2 * q]     = make_float2(a.x, a.y);
            p[2 * q + 1] = make_float2(a.z, a.w);
        }
        float vr = p[0].x, vi = p[0].y;
#pragma unroll
        for (int j = 1; j < 16; j++) {
            float nr2 = fmaf(wr, vr, fmaf(-wi, vi, p[j].x));
            float ni2 = fmaf(wi, vr, fmaf( wr, vi, p[j].y));
            vr = nr2; vi = ni2;
        }
        sre[t] = vr; sim_[t] = vi;
        float cwr = Wr, cwi = Wi;
        __syncthreads();
        for (int k = 1; k < BTH; k <<= 1) {
            float ore = 0.f, oim = 0.f;
            if (t >= k) { ore = sre[t - k]; oim = sim_[t - k]; }
            __syncthreads();
            vr += cwr * ore - cwi * oim;
            vi += cwr * oim + cwi * ore;
            sre[t] = vr; sim_[t] = vi;
            float nwr = cwr * cwr - cwi * cwi;
            cwi = 2.f * cwr * cwi; cwr = nwr;
            __syncthreads();
        }
        float er = 0.f, ei = 0.f;
        if (t > 0) { er = sre[t - 1]; ei = sim_[t - 1]; }
        float2 ec[16];
        ec[0] = make_float2(er, ei);
#pragma unroll
        for (int j = 1; j < 16; j++) {
            float nr2 = fmaf(wr, er, fmaf(-wi, ei, p[j - 1].x));
            float ni2 = fmaf(wi, er, fmaf( wr, ei, p[j - 1].y));
            er = nr2; ei = ni2;
            ec[j] = make_float2(er, ei);
        }
        float2* Cp = &g_C[mode * NCHUNK + 16 * t];
#pragma unroll
        for (int q = 0; q < 8; q++)
            *(float4*)&Cp[2 * q] = make_float4(ec[2 * q].x, ec[2 * q].y,
                                               ec[2 * q + 1].x, ec[2 * q + 1].y);
    }
    grid_barrier(&g_bar2);

    // ================= Phase C: carry-seeded output recurrence ===============
    {
        int row = tid >> 2, col = (tid & 3) * 2, c0 = blk * WPB;
        *(float4*)&sP[row][col] = *(const float4*)&g_C[row * NCHUNK + c0 + col];
    }
    __syncthreads();
    {
        float2 cA = sP[lane][warp], cB = sP[lane + 32][warp];
        u64 sr = pk2(cA.x, cB.x), si = pk2(cA.y, cB.y);
        float Dv = __ldg(D);
        float* rw = &red[warp][0];
        int gbase = base + warp * TCH;
#pragma unroll
        for (int tile = 0; tile < TCH / 32; tile++) {
#pragma unroll
            for (int i = 0; i < 32; i += 2) {
                float2 uu = *(const float2*)&su[warp * TCH + tile * 32 + i];
                u64 u1 = pk2(uu.x, uu.x), u2 = pk2(uu.y, uu.y);
                u64 tr = fma2(Zr, sr, fma2(nZi, si, u1));
                u64 ti = fma2(Zi, sr, mul2(Zr, si));
                u64 br = fma2(Zr, u1, u2), bi = mul2(Zi, u1);
                u64 vr = fma2(Z2r, sr, fma2(nZ2i, si, br));
                u64 vi = fma2(Z2i, sr, fma2(Z2r, si, bi));
                sr = vr; si = vi;
                u64 c1 = fma2(F, tr, mul2(nFi, ti));
                u64 c2 = fma2(F, vr, mul2(nFi, vi));
                float a0, a1, b0, b1;
                upk2(c1, a0, a1); upk2(c2, b0, b1);
                *(float2*)&rw[lane * 34 + i] = make_float2(a0 + a1, b0 + b1);
            }
            __syncwarp();
            float acc0 = 0.f, acc1 = 0.f, acc2 = 0.f, acc3 = 0.f;
#pragma unroll
            for (int l = 0; l < 32; l += 4) {
                acc0 += rw[(l + 0) * 34 + lane];
                acc1 += rw[(l + 1) * 34 + lane];
                acc2 += rw[(l + 2) * 34 + lane];
                acc3 += rw[(l + 3) * 34 + lane];
            }
            float uv = su[warp * TCH + tile * 32 + lane];
            y[gbase + tile * 32 + lane] = fmaf(Dv, uv, (acc0 + acc1) + (acc2 + acc3));
            __syncwarp();
        }
    }
}

extern "C" void kernel_launch(void* const* d_in, const int* in_sizes, int n_in,
                              void* d_out, int out_size) {
    const float* u        = (const float*)d_in[0];
    const float* A_re     = (const float*)d_in[1];
    const float* A_im     = (const float*)d_in[2];
    const float* C        = (const float*)d_in[3];
    const float* D        = (const float*)d_in[4];
    const float* log_step = (const float*)d_in[5];
    float* y = (float*)d_out;

    // Max smem carveout: 45KB/block and 47 regs allow ~5 blocks/SM, so all
    // 512 blocks are co-resident (barrier liveness).
    static int once = 0;
    if (!once) {
        cudaFuncSetAttribute(fused_kernel,
                             cudaFuncAttributePreferredSharedMemoryCarveout, 100);
        once = 1;
    }
    fused_kernel<<<NBLK, BTH>>>(u, A_re, A_im, C, D, log_step, y);
}